// round 4
// baseline (speedup 1.0000x reference)
#include <cuda_runtime.h>
#include <math.h>
#include <stdint.h>

// Problem constants: B=16, SEG=512, MEM=512, TOTAL=1024, MD=128, H=8, D=128

// ---------------- scratch ----------------
__device__ float g_h   [16 * 1024 * 128];          // concat(mem,x)      8 MB
__device__ float g_qf  [16 * 512 * 1024];          // x@Wq              32 MB
__device__ float g_kvf [16 * 1024 * 2048];         // h@Wkv            128 MB
__device__ float g_rf  [1024 * 1024];              // R@Wr               4 MB
__device__ float g_att [16 * 512 * 1024];          // attention out     32 MB
__device__ float g_y   [16 * 512 * 128];           // pre-LN y           4 MB

// ---------------- tf32 helpers ----------------
__device__ __forceinline__ uint32_t f2tf(float f) {
    uint32_t u; asm("cvt.rna.tf32.f32 %0, %1;" : "=r"(u) : "f"(f)); return u;
}
__device__ __forceinline__ uint4 cvt4(float4 v) {
    return make_uint4(f2tf(v.x), f2tf(v.y), f2tf(v.z), f2tf(v.w));
}
__device__ __forceinline__ void mma8(float4& c, const uint32_t a[4], uint32_t b0, uint32_t b1) {
    asm volatile("mma.sync.aligned.m16n8k8.row.col.f32.tf32.tf32.f32 "
        "{%0,%1,%2,%3}, {%4,%5,%6,%7}, {%8,%9}, {%0,%1,%2,%3};"
        : "+f"(c.x), "+f"(c.y), "+f"(c.z), "+f"(c.w)
        : "r"(a[0]), "r"(a[1]), "r"(a[2]), "r"(a[3]), "r"(b0), "r"(b1));
}

// ---------------- concat(mem, x) -> g_h ----------------
__global__ __launch_bounds__(256) void concat_kernel(
    const float* __restrict__ x, const float* __restrict__ mem, float* __restrict__ hout)
{
    long idx = (long)blockIdx.x * blockDim.x + threadIdx.x;
    long e = idx * 4;
    int b   = (int)(e >> 17);
    int rem = (int)(e & 131071);
    float4 v;
    if (rem < 65536)  v = *(const float4*)(mem + (long)b * 65536 + rem);
    else              v = *(const float4*)(x   + (long)b * 65536 + rem - 65536);
    *(float4*)(hout + e) = v;
}

// ---------------- tf32 NN GEMM (block 128x128, BK=32, 256 thr) ----------------
__global__ __launch_bounds__(256) void gemm_tf32(
    const float* __restrict__ Ab, const float* __restrict__ Bb, float* __restrict__ Cb,
    int M, int N, int K, long sA, long sB, long sC, const float* __restrict__ resid)
{
    const float* A = Ab + (long)blockIdx.z * sA;
    const float* B = Bb + (long)blockIdx.z * sB;
    float*       C = Cb + (long)blockIdx.z * sC;

    __shared__ __align__(16) uint32_t As[128 * 36];
    __shared__ __align__(16) uint32_t Bs[32 * 132];

    const int tid = threadIdx.x, lane = tid & 31, wid = tid >> 5;
    const int m0 = blockIdx.y << 7, n0 = blockIdx.x << 7;
    const int wm = (wid & 1) << 6;
    const int wn = (wid >> 1) << 5;
    const int g = lane >> 2, lt = lane & 3;

    const int am = tid >> 3, ak = (tid & 7) << 2;
    const int bk = tid >> 5, bn = (tid & 31) << 2;

    float4 acc[4][4];
#pragma unroll
    for (int t = 0; t < 4; t++)
#pragma unroll
        for (int s = 0; s < 4; s++) acc[t][s] = make_float4(0.f, 0.f, 0.f, 0.f);

    for (int k0 = 0; k0 < K; k0 += 32) {
        uint4 ta[4], tb[4];
#pragma unroll
        for (int it = 0; it < 4; it++) {
            ta[it] = cvt4(*(const float4*)(A + (long)(m0 + am + (it << 5)) * K + k0 + ak));
            tb[it] = cvt4(*(const float4*)(B + (long)(k0 + bk + (it << 3)) * N + n0 + bn));
        }
        __syncthreads();
#pragma unroll
        for (int it = 0; it < 4; it++) {
            *(uint4*)&As[(am + (it << 5)) * 36 + ak] = ta[it];
            *(uint4*)&Bs[(bk + (it << 3)) * 132 + bn] = tb[it];
        }
        __syncthreads();
#pragma unroll
        for (int kk = 0; kk < 4; kk++) {
            const int kb = kk << 3;
            uint32_t af[4][4];
#pragma unroll
            for (int t = 0; t < 4; t++) {
                int row = wm + (t << 4) + g;
                af[t][0] = As[row * 36 + kb + lt];
                af[t][1] = As[(row + 8) * 36 + kb + lt];
                af[t][2] = As[row * 36 + kb + lt + 4];
                af[t][3] = As[(row + 8) * 36 + kb + lt + 4];
            }
#pragma unroll
            for (int s = 0; s < 4; s++) {
                int col = wn + (s << 3) + g;
                uint32_t b0 = Bs[(kb + lt) * 132 + col];
                uint32_t b1 = Bs[(kb + lt + 4) * 132 + col];
#pragma unroll
                for (int t = 0; t < 4; t++) mma8(acc[t][s], af[t], b0, b1);
            }
        }
    }

#pragma unroll
    for (int t = 0; t < 4; t++) {
        int r0 = m0 + wm + (t << 4) + g;
#pragma unroll
        for (int s = 0; s < 4; s++) {
            int c = n0 + wn + (s << 3) + (lt << 1);
            float2 v0 = make_float2(acc[t][s].x, acc[t][s].y);
            float2 v1 = make_float2(acc[t][s].z, acc[t][s].w);
            if (resid) {
                float2 r4 = *(const float2*)(resid + (long)r0 * N + c);
                v0.x += r4.x; v0.y += r4.y;
                float2 r5 = *(const float2*)(resid + (long)(r0 + 8) * N + c);
                v1.x += r5.x; v1.y += r5.y;
            }
            *(float2*)(C + (long)r0 * N + c) = v0;
            *(float2*)(C + (long)(r0 + 8) * N + c) = v1;
        }
    }
}

// ---------------- fused flash attention (scores + online softmax + P@V) ----------------
// Grid: (i_tile=8, z=128). Block 256 threads, 8 warps. 64-row Q tile per block.
// Dynamic smem layout (bytes):
//   Q1s (q+u1, tf32)  [64][132]  @ 0       (33792)
//   Q2s (q+u2, tf32)  [64][132]  @ 33792   (33792)
//   Gs  (BD panel f32)[64][132]  @ 67584   (33792)
//   Ps  (P tf32)      [64][68]   @ 101376  (17408)
//   Ks  (K tf32)      [64][36]   @ 118784  (9216)   } overlaid by
//   Rs  (r tf32)      [128][36]  @ 128000  (18432)  } Vs [32][136] @ 118784 (17408)
//   m_row/l_row/redM/redS/redMn/redF                @ 146432..148480
#define FLASH_SMEM 148480

__global__ __launch_bounds__(256) void flash_tf32(
    const float* __restrict__ qf, const float* __restrict__ kvf,
    const float* __restrict__ rf, const float* __restrict__ U1,
    const float* __restrict__ U2, float* __restrict__ att)
{
    extern __shared__ char dsm[];
    uint32_t* Q1s = (uint32_t*)dsm;
    uint32_t* Q2s = (uint32_t*)(dsm + 33792);
    float*    Gs  = (float*)(dsm + 67584);
    uint32_t* Ps  = (uint32_t*)(dsm + 101376);
    uint32_t* Ks  = (uint32_t*)(dsm + 118784);
    uint32_t* Rs  = (uint32_t*)(dsm + 128000);
    uint32_t* Vs  = (uint32_t*)(dsm + 118784);
    float* m_row = (float*)(dsm + 146432);
    float* l_row = (float*)(dsm + 146688);
    float* redM  = (float*)(dsm + 146944);   // [2][64]
    float* redS  = (float*)(dsm + 147456);   // [2][64]
    float* redMn = (float*)(dsm + 147968);
    float* redF  = (float*)(dsm + 148224);

    const int it = blockIdx.x, z = blockIdx.y, h = z & 7;
    const int i0 = it << 6;
    const float* Q  = qf + (long)z * 65536;
    const float* Kg = kvf + (long)z * 131072;
    const float* Vg = kvf + 16777216L + (long)z * 131072;
    const float* Rh = rf + (long)h * 131072;

    const int tid = threadIdx.x, lane = tid & 31, w = tid >> 5;
    const int g = lane >> 2, lt = lane & 3;

    // Build Q1s = tf32(q+u1), Q2s = tf32(q+u2)
    {
        const int qm = tid >> 2, qc0 = (tid & 3) << 5;
        const float* u1p = U1 + (h << 7);
        const float* u2p = U2 + (h << 7);
        const float* qp = Q + (long)(i0 + qm) * 128;
#pragma unroll
        for (int f = 0; f < 8; f++) {
            int c = qc0 + (f << 2);
            float4 qv = *(const float4*)(qp + c);
            float4 a  = *(const float4*)(u1p + c);
            float4 b  = *(const float4*)(u2p + c);
            *(uint4*)&Q1s[qm * 132 + c] =
                cvt4(make_float4(qv.x + a.x, qv.y + a.y, qv.z + a.z, qv.w + a.w));
            *(uint4*)&Q2s[qm * 132 + c] =
                cvt4(make_float4(qv.x + b.x, qv.y + b.y, qv.z + b.z, qv.w + b.w));
        }
    }
    if (tid < 64) { m_row[tid] = -1e30f; l_row[tid] = 0.f; }

    const int wm = (w & 3) << 4, half = w >> 2;
    const int wn = half << 5;               // AC cols (32 per half)
    const int wc = half << 6;               // BD cols (64 per half)
    const int rg = (w & 1) << 5, cg = (w >> 1) << 5;   // PV/O tiling: 32x32 per warp

    float4 acO[2][4];
#pragma unroll
    for (int t = 0; t < 2; t++)
#pragma unroll
        for (int s = 0; s < 4; s++) acO[t][s] = make_float4(0.f, 0.f, 0.f, 0.f);

    const int njt = it + 9;
    const float inv = 0.08838834764831845f;     // 1/sqrt(128)
    const int rlo = wm + g, rhi = wm + g + 8;

    for (int jt = 0; jt < njt; jt++) {
        const int j0 = jt << 6;
        const int cbase = 448 + j0 - i0;        // >= 0
        const int lim = i0 - j0 + 512;          // valid iff (cl - rl) <= lim
        float4 acA[4], acB[8];
#pragma unroll
        for (int s = 0; s < 4; s++) acA[s] = make_float4(0.f, 0.f, 0.f, 0.f);
#pragma unroll
        for (int s = 0; s < 8; s++) acB[s] = make_float4(0.f, 0.f, 0.f, 0.f);

        // ---- phase A: S = (q+u1)K^T (acA) and BD panel (q+u2)r^T (acB) ----
#pragma unroll
        for (int k0 = 0; k0 < 128; k0 += 32) {
            const int kr = tid >> 2, kc = (tid & 3) << 3;
            const float* kp = Kg + (long)(j0 + kr) * 128 + k0 + kc;
            uint4 t0 = cvt4(*(const float4*)(kp));
            uint4 t1 = cvt4(*(const float4*)(kp + 4));
            const int rr = tid >> 1, rc = (tid & 1) << 4;
            int cr = cbase + rr; if (cr > 1023) cr = 1023;   // clamped rows masked anyway
            const float* rp = Rh + (long)cr * 128 + k0 + rc;
            uint4 r0 = cvt4(*(const float4*)(rp));
            uint4 r1 = cvt4(*(const float4*)(rp + 4));
            uint4 r2 = cvt4(*(const float4*)(rp + 8));
            uint4 r3 = cvt4(*(const float4*)(rp + 12));
            __syncthreads();
            *(uint4*)&Ks[kr * 36 + kc]     = t0;
            *(uint4*)&Ks[kr * 36 + kc + 4] = t1;
            *(uint4*)&Rs[rr * 36 + rc]      = r0;
            *(uint4*)&Rs[rr * 36 + rc + 4]  = r1;
            *(uint4*)&Rs[rr * 36 + rc + 8]  = r2;
            *(uint4*)&Rs[rr * 36 + rc + 12] = r3;
            __syncthreads();
#pragma unroll
            for (int kb = 0; kb < 32; kb += 8) {
                const int ka = k0 + kb + lt;
                uint32_t a1[4] = { Q1s[rlo * 132 + ka], Q1s[rhi * 132 + ka],
                                   Q1s[rlo * 132 + ka + 4], Q1s[rhi * 132 + ka + 4] };
                uint32_t a2[4] = { Q2s[rlo * 132 + ka], Q2s[rhi * 132 + ka],
                                   Q2s[rlo * 132 + ka + 4], Q2s[rhi * 132 + ka + 4] };
#pragma unroll
                for (int s = 0; s < 4; s++) {
                    int n = (wn + (s << 3) + g) * 36 + kb + lt;
                    mma8(acA[s], a1, Ks[n], Ks[n + 4]);
                }
#pragma unroll
                for (int s = 0; s < 8; s++) {
                    int n = (wc + (s << 3) + g) * 36 + kb + lt;
                    mma8(acB[s], a2, Rs[n], Rs[n + 4]);
                }
            }
        }

        // ---- BD panel to smem, then diagonal gather ----
#pragma unroll
        for (int s = 0; s < 8; s++) {
            int c = wc + (s << 3) + (lt << 1);
            *(float2*)&Gs[rlo * 132 + c] = make_float2(acB[s].x, acB[s].y);
            *(float2*)&Gs[rhi * 132 + c] = make_float2(acB[s].z, acB[s].w);
        }
        __syncthreads();

        float sv[16];
        float mxlo = -1e30f, mxhi = -1e30f;
#pragma unroll
        for (int s = 0; s < 4; s++) {
            int cl = wn + (s << 3) + (lt << 1);
            float v0 = (acA[s].x + Gs[rlo * 132 + 63 + cl - rlo]) * inv;
            float v1 = (acA[s].y + Gs[rlo * 132 + 64 + cl - rlo]) * inv;
            float v2 = (acA[s].z + Gs[rhi * 132 + 63 + cl - rhi]) * inv;
            float v3 = (acA[s].w + Gs[rhi * 132 + 64 + cl - rhi]) * inv;
            if (cl     - rlo > lim) v0 = -1e30f;
            if (cl + 1 - rlo > lim) v1 = -1e30f;
            if (cl     - rhi > lim) v2 = -1e30f;
            if (cl + 1 - rhi > lim) v3 = -1e30f;
            sv[s * 4 + 0] = v0; sv[s * 4 + 1] = v1; sv[s * 4 + 2] = v2; sv[s * 4 + 3] = v3;
            mxlo = fmaxf(mxlo, fmaxf(v0, v1));
            mxhi = fmaxf(mxhi, fmaxf(v2, v3));
        }
        mxlo = fmaxf(mxlo, __shfl_xor_sync(0xffffffffu, mxlo, 1));
        mxlo = fmaxf(mxlo, __shfl_xor_sync(0xffffffffu, mxlo, 2));
        mxhi = fmaxf(mxhi, __shfl_xor_sync(0xffffffffu, mxhi, 1));
        mxhi = fmaxf(mxhi, __shfl_xor_sync(0xffffffffu, mxhi, 2));
        if (lt == 0) { redM[half * 64 + rlo] = mxlo; redM[half * 64 + rhi] = mxhi; }
        __syncthreads();

        if (w < 4 && lt == 0) {
#pragma unroll
            for (int e = 0; e < 2; e++) {
                int r = wm + g + (e << 3);
                float mo = m_row[r];
                float mn = fmaxf(mo, fmaxf(redM[r], redM[64 + r]));
                redMn[r] = mn;
                redF[r]  = __expf(mo - mn);
            }
        }
        __syncthreads();

        // ---- P = exp(S - m_new), partial sums, store P (tf32) ----
        float mnlo = redMn[rlo], mnhi = redMn[rhi];
        float slo = 0.f, shi = 0.f;
#pragma unroll
        for (int s = 0; s < 4; s++) {
            int cl = wn + (s << 3) + (lt << 1);
            float p0 = __expf(sv[s * 4 + 0] - mnlo);
            float p1 = __expf(sv[s * 4 + 1] - mnlo);
            float p2 = __expf(sv[s * 4 + 2] - mnhi);
            float p3 = __expf(sv[s * 4 + 3] - mnhi);
            slo += p0 + p1; shi += p2 + p3;
            Ps[rlo * 68 + cl]     = f2tf(p0);
            Ps[rlo * 68 + cl + 1] = f2tf(p1);
            Ps[rhi * 68 + cl]     = f2tf(p2);
            Ps[rhi * 68 + cl + 1] = f2tf(p3);
        }
        slo += __shfl_xor_sync(0xffffffffu, slo, 1);
        slo += __shfl_xor_sync(0xffffffffu, slo, 2);
        shi += __shfl_xor_sync(0xffffffffu, shi, 1);
        shi += __shfl_xor_sync(0xffffffffu, shi, 2);
        if (lt == 0) { redS[half * 64 + rlo] = slo; redS[half * 64 + rhi] = shi; }

        // rescale O accumulators by exp(m_old - m_new) for their rows
        {
            float f0 = redF[rg + g], f1 = redF[rg + g + 8];
            float f2 = redF[rg + 16 + g], f3 = redF[rg + 16 + g + 8];
#pragma unroll
            for (int s = 0; s < 4; s++) {
                acO[0][s].x *= f0; acO[0][s].y *= f0; acO[0][s].z *= f1; acO[0][s].w *= f1;
                acO[1][s].x *= f2; acO[1][s].y *= f2; acO[1][s].z *= f3; acO[1][s].w *= f3;
            }
        }
        __syncthreads();

        if (w < 4 && lt == 0) {
#pragma unroll
            for (int e = 0; e < 2; e++) {
                int r = wm + g + (e << 3);
                l_row[r] = l_row[r] * redF[r] + redS[r] + redS[64 + r];
                m_row[r] = redMn[r];
            }
        }

        // ---- phase B: O += P @ V ----
#pragma unroll
        for (int kc0 = 0; kc0 < 64; kc0 += 32) {
            const int vr = tid >> 3, vc = (tid & 7) << 4;
            const float* vp = Vg + (long)(j0 + kc0 + vr) * 128 + vc;
            uint4 v0 = cvt4(*(const float4*)(vp));
            uint4 v1 = cvt4(*(const float4*)(vp + 4));
            uint4 v2 = cvt4(*(const float4*)(vp + 8));
            uint4 v3 = cvt4(*(const float4*)(vp + 12));
            __syncthreads();
            *(uint4*)&Vs[vr * 136 + vc]      = v0;
            *(uint4*)&Vs[vr * 136 + vc + 4]  = v1;
            *(uint4*)&Vs[vr * 136 + vc + 8]  = v2;
            *(uint4*)&Vs[vr * 136 + vc + 12] = v3;
            __syncthreads();
#pragma unroll
            for (int kb = 0; kb < 32; kb += 8) {
#pragma unroll
                for (int t = 0; t < 2; t++) {
                    int rb = rg + (t << 4) + g;
                    uint32_t a[4] = { Ps[rb * 68 + kc0 + kb + lt],
                                      Ps[(rb + 8) * 68 + kc0 + kb + lt],
                                      Ps[rb * 68 + kc0 + kb + lt + 4],
                                      Ps[(rb + 8) * 68 + kc0 + kb + lt + 4] };
#pragma unroll
                    for (int s = 0; s < 4; s++) {
                        int n = cg + (s << 3) + g;
                        mma8(acO[t][s], a, Vs[(kb + lt) * 136 + n], Vs[(kb + lt + 4) * 136 + n]);
                    }
                }
            }
        }
    }

    // ---- epilogue: O / l_row -> att (z-major flat layout) ----
    __syncthreads();
    float il0 = 1.f / l_row[rg + g],      il1 = 1.f / l_row[rg + g + 8];
    float il2 = 1.f / l_row[rg + 16 + g], il3 = 1.f / l_row[rg + 16 + g + 8];
    float* ap = att + (long)z * 65536;
#pragma unroll
    for (int t = 0; t < 2; t++) {
        float flo = t ? il2 : il0, fhi = t ? il3 : il1;
#pragma unroll
        for (int s = 0; s < 4; s++) {
            int row = i0 + rg + (t << 4) + g;
            int col = cg + (s << 3) + (lt << 1);
            *(float2*)(ap + (long)row * 128 + col) =
                make_float2(acO[t][s].x * flo, acO[t][s].y * flo);
            *(float2*)(ap + (long)(row + 8) * 128 + col) =
                make_float2(acO[t][s].z * fhi, acO[t][s].w * fhi);
        }
    }
}

// ---------------- LayerNorm over last dim (128) ----------------
__global__ __launch_bounds__(256) void ln_kernel(
    const float* __restrict__ Y, const float* __restrict__ gamma,
    const float* __restrict__ beta, float* __restrict__ out)
{
    const int row  = (blockIdx.x << 3) + (threadIdx.x >> 5);
    const int lane = threadIdx.x & 31;
    const float* y = Y + (long)row * 128;

    float4 v = *(const float4*)(y + (lane << 2));
    float s = v.x + v.y + v.z + v.w;
#pragma unroll
    for (int o = 16; o > 0; o >>= 1) s += __shfl_xor_sync(0xffffffffu, s, o);
    float mu = s * (1.0f / 128.0f);

    float dx = v.x - mu, dy = v.y - mu, dz = v.z - mu, dw = v.w - mu;
    float q = dx * dx + dy * dy + dz * dz + dw * dw;
#pragma unroll
    for (int o = 16; o > 0; o >>= 1) q += __shfl_xor_sync(0xffffffffu, q, o);
    float inv = rsqrtf(q * (1.0f / 128.0f) + 1e-5f);

    float4 g  = *(const float4*)(gamma + (lane << 2));
    float4 b4 = *(const float4*)(beta + (lane << 2));
    float4 o4;
    o4.x = dx * inv * g.x + b4.x;
    o4.y = dy * inv * g.y + b4.y;
    o4.z = dz * inv * g.z + b4.z;
    o4.w = dw * inv * g.w + b4.w;
    *(float4*)(out + (long)row * 128 + (lane << 2)) = o4;
}

// ---------------- launch ----------------
extern "C" void kernel_launch(void* const* d_in, const int* in_sizes, int n_in,
                              void* d_out, int out_size)
{
    const float* x     = (const float*)d_in[0];
    const float* mem   = (const float*)d_in[1];
    const float* R     = (const float*)d_in[2];
    // d_in[3] = att_mask (all ones; unused by reference)
    const float* u1    = (const float*)d_in[4];
    const float* u2    = (const float*)d_in[5];
    const float* Wq    = (const float*)d_in[6];
    const float* Wkv   = (const float*)d_in[7];
    const float* Wr    = (const float*)d_in[8];
    const float* Wmlp  = (const float*)d_in[9];
    const float* gamma = (const float*)d_in[10];
    const float* beta  = (const float*)d_in[11];
    float* out = (float*)d_out;

    float *hb, *qf, *kvf, *rf, *att, *yb;
    cudaGetSymbolAddress((void**)&hb,  g_h);
    cudaGetSymbolAddress((void**)&qf,  g_qf);
    cudaGetSymbolAddress((void**)&kvf, g_kvf);
    cudaGetSymbolAddress((void**)&rf,  g_rf);
    cudaGetSymbolAddress((void**)&att, g_att);
    cudaGetSymbolAddress((void**)&yb,  g_y);

    cudaFuncSetAttribute(flash_tf32, cudaFuncAttributeMaxDynamicSharedMemorySize, FLASH_SMEM);

    // 1) h = concat(mem, x)
    concat_kernel<<<2048, 256>>>(x, mem, hb);
    // 2) qf = x @ Wq            (8192 x 1024, K=128)
    gemm_tf32<<<dim3(8, 64, 1), 256>>>(x, Wq, qf, 8192, 1024, 128, 0, 0, 0, nullptr);
    // 3) kvf = h @ Wkv          (16384 x 2048, K=128)
    gemm_tf32<<<dim3(16, 128, 1), 256>>>(hb, Wkv, kvf, 16384, 2048, 128, 0, 0, 0, nullptr);
    // 4) rf = R @ Wr            (1024 x 1024, K=128)
    gemm_tf32<<<dim3(8, 8, 1), 256>>>(R, Wr, rf, 1024, 1024, 128, 0, 0, 0, nullptr);
    // 5) fused attention: scores (AC + circulant BD) -> online softmax -> P@V
    flash_tf32<<<dim3(8, 128), 256, FLASH_SMEM>>>(qf, kvf, rf, u1, u2, att);
    // 6) y = att @ Wmlp + x     (8192 x 128, K=1024)
    gemm_tf32<<<dim3(1, 64, 1), 256>>>(att, Wmlp, yb, 8192, 128, 1024, 0, 0, 0, x);
    // 7) out = LayerNorm(y) * gamma + beta
    ln_kernel<<<1024, 256>>>(yb, gamma, beta, out);
}

// round 5
// speedup vs baseline: 1.2493x; 1.2493x over previous
#include <cuda_runtime.h>
#include <math.h>
#include <stdint.h>

// Problem constants: B=16, SEG=512, MEM=512, TOTAL=1024, MD=128, H=8, D=128

// ---------------- scratch ----------------
__device__ float g_h   [16 * 1024 * 128];          // concat(mem,x)      8 MB
__device__ float g_qf  [16 * 512 * 1024];          // x@Wq              32 MB
__device__ float g_kvf [16 * 1024 * 2048];         // h@Wkv            128 MB
__device__ float g_rf  [1024 * 1024];              // R@Wr               4 MB
__device__ float g_g   [128ll * 512 * 1024];       // G=(q+u2)@r^T     256 MB
__device__ float g_s   [128ll * 512 * 1024];       // scores/probs     256 MB
__device__ float g_att [16 * 512 * 1024];          // attention out     32 MB
__device__ float g_y   [16 * 512 * 128];           // pre-LN y           4 MB

// ---------------- tf32 helpers ----------------
__device__ __forceinline__ uint32_t f2tf(float f) {
    uint32_t u; asm("cvt.rna.tf32.f32 %0, %1;" : "=r"(u) : "f"(f)); return u;
}
__device__ __forceinline__ uint4 cvt4(float4 v) {
    return make_uint4(f2tf(v.x), f2tf(v.y), f2tf(v.z), f2tf(v.w));
}
__device__ __forceinline__ float4 add4(float4 a, float4 b) {
    return make_float4(a.x + b.x, a.y + b.y, a.z + b.z, a.w + b.w);
}
__device__ __forceinline__ void mma8(float4& c, const uint32_t a[4], uint32_t b0, uint32_t b1) {
    asm volatile("mma.sync.aligned.m16n8k8.row.col.f32.tf32.tf32.f32 "
        "{%0,%1,%2,%3}, {%4,%5,%6,%7}, {%8,%9}, {%0,%1,%2,%3};"
        : "+f"(c.x), "+f"(c.y), "+f"(c.z), "+f"(c.w)
        : "r"(a[0]), "r"(a[1]), "r"(a[2]), "r"(a[3]), "r"(b0), "r"(b1));
}

// ---------------- concat(mem, x) -> g_h ----------------
__global__ __launch_bounds__(256) void concat_kernel(
    const float* __restrict__ x, const float* __restrict__ mem, float* __restrict__ hout)
{
    long idx = (long)blockIdx.x * blockDim.x + threadIdx.x;
    long e = idx * 4;
    int b   = (int)(e >> 17);
    int rem = (int)(e & 131071);
    float4 v;
    if (rem < 65536)  v = *(const float4*)(mem + (long)b * 65536 + rem);
    else              v = *(const float4*)(x   + (long)b * 65536 + rem - 65536);
    *(float4*)(hout + e) = v;
}

// ---------------- tf32 NN GEMM (block 128x128, BK=32, 256 thr) ----------------
// kcap != 0: K_eff = min(K, m0 + kcap)  (causal skip for P@V)
__global__ __launch_bounds__(256) void gemm_tf32(
    const float* __restrict__ Ab, const float* __restrict__ Bb, float* __restrict__ Cb,
    int M, int N, int K, long sA, long sB, long sC, const float* __restrict__ resid,
    int kcap)
{
    const float* A = Ab + (long)blockIdx.z * sA;
    const float* B = Bb + (long)blockIdx.z * sB;
    float*       C = Cb + (long)blockIdx.z * sC;

    __shared__ __align__(16) uint32_t As[128 * 36];
    __shared__ __align__(16) uint32_t Bs[32 * 132];

    const int tid = threadIdx.x, lane = tid & 31, wid = tid >> 5;
    const int m0 = blockIdx.y << 7, n0 = blockIdx.x << 7;
    const int wm = (wid & 1) << 6;
    const int wn = (wid >> 1) << 5;
    const int g = lane >> 2, lt = lane & 3;

    const int am = tid >> 3, ak = (tid & 7) << 2;
    const int bk = tid >> 5, bn = (tid & 31) << 2;

    int Ke = K;
    if (kcap) { Ke = m0 + kcap; if (Ke > K) Ke = K; }

    float4 acc[4][4];
#pragma unroll
    for (int t = 0; t < 4; t++)
#pragma unroll
        for (int s = 0; s < 4; s++) acc[t][s] = make_float4(0.f, 0.f, 0.f, 0.f);

    for (int k0 = 0; k0 < Ke; k0 += 32) {
        uint4 ta[4], tb[4];
#pragma unroll
        for (int it = 0; it < 4; it++) {
            ta[it] = cvt4(*(const float4*)(A + (long)(m0 + am + (it << 5)) * K + k0 + ak));
            tb[it] = cvt4(*(const float4*)(B + (long)(k0 + bk + (it << 3)) * N + n0 + bn));
        }
        __syncthreads();
#pragma unroll
        for (int it = 0; it < 4; it++) {
            *(uint4*)&As[(am + (it << 5)) * 36 + ak] = ta[it];
            *(uint4*)&Bs[(bk + (it << 3)) * 132 + bn] = tb[it];
        }
        __syncthreads();
#pragma unroll
        for (int kk = 0; kk < 4; kk++) {
            const int kb = kk << 3;
            uint32_t af[4][4];
#pragma unroll
            for (int t = 0; t < 4; t++) {
                int row = wm + (t << 4) + g;
                af[t][0] = As[row * 36 + kb + lt];
                af[t][1] = As[(row + 8) * 36 + kb + lt];
                af[t][2] = As[row * 36 + kb + lt + 4];
                af[t][3] = As[(row + 8) * 36 + kb + lt + 4];
            }
#pragma unroll
            for (int s = 0; s < 4; s++) {
                int col = wn + (s << 3) + g;
                uint32_t b0 = Bs[(kb + lt) * 132 + col];
                uint32_t b1 = Bs[(kb + lt + 4) * 132 + col];
#pragma unroll
                for (int t = 0; t < 4; t++) mma8(acc[t][s], af[t], b0, b1);
            }
        }
    }

#pragma unroll
    for (int t = 0; t < 4; t++) {
        int r0 = m0 + wm + (t << 4) + g;
#pragma unroll
        for (int s = 0; s < 4; s++) {
            int c = n0 + wn + (s << 3) + (lt << 1);
            float2 v0 = make_float2(acc[t][s].x, acc[t][s].y);
            float2 v1 = make_float2(acc[t][s].z, acc[t][s].w);
            if (resid) {
                float2 r4 = *(const float2*)(resid + (long)r0 * N + c);
                v0.x += r4.x; v0.y += r4.y;
                float2 r5 = *(const float2*)(resid + (long)(r0 + 8) * N + c);
                v1.x += r5.x; v1.y += r5.y;
            }
            *(float2*)(C + (long)r0 * N + c) = v0;
            *(float2*)(C + (long)(r0 + 8) * N + c) = v1;
        }
    }
}

// ---------------- G = (q + u2) @ r^T, per z (512 x 1024), tf32 NT GEMM ----------------
// Grid (8 c-tiles, 4 r-tiles, 128 z). Tile 128x128, BK=32.
// Tile skipped if max(i)+max(c) < 511 (entries never referenced by the gather).
__global__ __launch_bounds__(256) void gemm_nt_g(
    const float* __restrict__ qf, const float* __restrict__ rf,
    const float* __restrict__ U2, float* __restrict__ Gg)
{
    const int r0 = blockIdx.y << 7, c0 = blockIdx.x << 7;
    if (r0 + c0 + 254 < 511) return;     // never-used region of G
    const int z = blockIdx.z, h = z & 7;
    const float* A  = qf + (long)z * 65536;
    const float* Bm = rf + (long)h * 131072;
    float*       G  = Gg + (long)z * 524288;

    __shared__ __align__(16) uint32_t As[128 * 36];   // [m][k]
    __shared__ __align__(16) uint32_t Bs[128 * 36];   // [n][k]
    __shared__ float u2s[128];

    const int tid = threadIdx.x, lane = tid & 31, wid = tid >> 5;
    const int wm = (wid & 1) << 6;
    const int wn = (wid >> 1) << 5;
    const int g = lane >> 2, lt = lane & 3;
    const int am = tid >> 3, ak = (tid & 7) << 2;

    if (tid < 128) u2s[tid] = U2[(h << 7) + tid];
    __syncthreads();

    float4 acc[4][4];
#pragma unroll
    for (int t = 0; t < 4; t++)
#pragma unroll
        for (int s = 0; s < 4; s++) acc[t][s] = make_float4(0.f, 0.f, 0.f, 0.f);

#pragma unroll
    for (int k0 = 0; k0 < 128; k0 += 32) {
        float4 u4 = *(const float4*)&u2s[k0 + ak];
        uint4 ta[4], tb[4];
#pragma unroll
        for (int it = 0; it < 4; it++) {
            float4 av = *(const float4*)(A  + (long)(r0 + am + (it << 5)) * 128 + k0 + ak);
            ta[it] = cvt4(add4(av, u4));
            tb[it] = cvt4(*(const float4*)(Bm + (long)(c0 + am + (it << 5)) * 128 + k0 + ak));
        }
        __syncthreads();
#pragma unroll
        for (int it = 0; it < 4; it++) {
            *(uint4*)&As[(am + (it << 5)) * 36 + ak] = ta[it];
            *(uint4*)&Bs[(am + (it << 5)) * 36 + ak] = tb[it];
        }
        __syncthreads();
#pragma unroll
        for (int kk = 0; kk < 4; kk++) {
            const int kb = kk << 3;
            uint32_t af[4][4];
#pragma unroll
            for (int t = 0; t < 4; t++) {
                int row = wm + (t << 4) + g;
                af[t][0] = As[row * 36 + kb + lt];
                af[t][1] = As[(row + 8) * 36 + kb + lt];
                af[t][2] = As[row * 36 + kb + lt + 4];
                af[t][3] = As[(row + 8) * 36 + kb + lt + 4];
            }
#pragma unroll
            for (int s = 0; s < 4; s++) {
                int n = (wn + (s << 3) + g) * 36 + kb + lt;
                uint32_t b0 = Bs[n], b1 = Bs[n + 4];
#pragma unroll
                for (int t = 0; t < 4; t++) mma8(acc[t][s], af[t], b0, b1);
            }
        }
    }

#pragma unroll
    for (int t = 0; t < 4; t++) {
        int rr = r0 + wm + (t << 4) + g;
#pragma unroll
        for (int s = 0; s < 4; s++) {
            int c = c0 + wn + (s << 3) + (lt << 1);
            *(float2*)(G + (long)rr * 1024 + c) = make_float2(acc[t][s].x, acc[t][s].y);
            *(float2*)(G + (long)(rr + 8) * 1024 + c) = make_float2(acc[t][s].z, acc[t][s].w);
        }
    }
}

// ---------------- score kernel: S = ((q+u1)@k^T + gather(G)) / sqrt(d) ----------------
// 64x64 tile, 256 threads, 8 warps: warp = 16 rows x 32 cols (half).
__global__ __launch_bounds__(256) void score_ac(
    const float* __restrict__ qf, const float* __restrict__ kvf,
    const float* __restrict__ Gg, const float* __restrict__ U1,
    float* __restrict__ Sb)
{
    if (blockIdx.x > blockIdx.y + 8) return;           // fully masked tile
    const int z = blockIdx.z, h = z & 7;
    const int i0 = blockIdx.y << 6, j0 = blockIdx.x << 6;
    const float* Q  = qf + (long)z * 65536;
    const float* Kg = kvf + (long)z * 131072;
    const float* Gz = Gg + (long)z * 524288;
    float*       S  = Sb + (long)z * 524288;

    __shared__ __align__(16) uint32_t Qs[64 * 36];
    __shared__ __align__(16) uint32_t Ks[64 * 36];
    __shared__ float u1s[128];

    const int tid = threadIdx.x, lane = tid & 31, w = tid >> 5;
    const int g = lane >> 2, lt = lane & 3;
    const int wm = (w & 3) << 4, half = w >> 2;
    const int wn = half << 5;
    const int rlo = wm + g, rhi = rlo + 8;
    const int qm = tid >> 2, qc = (tid & 3) << 3;

    if (tid < 128) u1s[tid] = U1[(h << 7) + tid];
    __syncthreads();

    float4 acA[4];
#pragma unroll
    for (int s = 0; s < 4; s++) acA[s] = make_float4(0.f, 0.f, 0.f, 0.f);

#pragma unroll
    for (int k0 = 0; k0 < 128; k0 += 32) {
        float4 u4a = *(const float4*)&u1s[k0 + qc];
        float4 u4b = *(const float4*)&u1s[k0 + qc + 4];
        const float* qp = Q  + (long)(i0 + qm) * 128 + k0 + qc;
        const float* kp = Kg + (long)(j0 + qm) * 128 + k0 + qc;
        uint4 tq0 = cvt4(add4(*(const float4*)(qp), u4a));
        uint4 tq1 = cvt4(add4(*(const float4*)(qp + 4), u4b));
        uint4 tk0 = cvt4(*(const float4*)(kp));
        uint4 tk1 = cvt4(*(const float4*)(kp + 4));
        __syncthreads();
        *(uint4*)&Qs[qm * 36 + qc]     = tq0;
        *(uint4*)&Qs[qm * 36 + qc + 4] = tq1;
        *(uint4*)&Ks[qm * 36 + qc]     = tk0;
        *(uint4*)&Ks[qm * 36 + qc + 4] = tk1;
        __syncthreads();
#pragma unroll
        for (int kb = 0; kb < 32; kb += 8) {
            uint32_t a1[4] = { Qs[rlo * 36 + kb + lt], Qs[rhi * 36 + kb + lt],
                               Qs[rlo * 36 + kb + lt + 4], Qs[rhi * 36 + kb + lt + 4] };
#pragma unroll
            for (int s = 0; s < 4; s++) {
                int n = (wn + (s << 3) + g) * 36 + kb + lt;
                mma8(acA[s], a1, Ks[n], Ks[n + 4]);
            }
        }
    }

    const float inv = 0.08838834764831845f;   // 1/sqrt(128)
    const int iA = i0 + rlo, iB = i0 + rhi;
    const float* GA = Gz + (long)iA * 1024 + 511 - iA;
    const float* GB = Gz + (long)iB * 1024 + 511 - iB;
    float* SA = S + (long)iA * 1024;
    float* SB = S + (long)iB * 1024;
#pragma unroll
    for (int s = 0; s < 4; s++) {
        int jA = j0 + wn + (s << 3) + (lt << 1);
        if (jA     <= iA + 512) SA[jA]     = (acA[s].x + GA[jA])     * inv;
        if (jA + 1 <= iA + 512) SA[jA + 1] = (acA[s].y + GA[jA + 1]) * inv;
        if (jA     <= iB + 512) SB[jA]     = (acA[s].z + GB[jA])     * inv;
        if (jA + 1 <= iB + 512) SB[jA + 1] = (acA[s].w + GB[jA + 1]) * inv;
    }
}

// ---------------- causal softmax, banded (valid width = i+513) ----------------
__global__ __launch_bounds__(256) void softmax_kernel(float* __restrict__ S)
{
    const int row  = (blockIdx.x << 3) + (threadIdx.x >> 5);
    const int lane = threadIdx.x & 31;
    const int i = row & 511;
    const int valid = i + 513;
    const int nch = (i + 640) >> 7;           // chunks of 128 needed (5..8)
    float* p = S + (long)row * 1024;

    float4 v[8];
    float mx = -3.402823466e38f;
#pragma unroll
    for (int c2 = 0; c2 < 8; c2++) {
        if (c2 >= nch) continue;
        int jb = (c2 << 7) + (lane << 2);
        v[c2] = *(const float4*)(p + jb);
        if (jb + 0 < valid) mx = fmaxf(mx, v[c2].x);
        if (jb + 1 < valid) mx = fmaxf(mx, v[c2].y);
        if (jb + 2 < valid) mx = fmaxf(mx, v[c2].z);
        if (jb + 3 < valid) mx = fmaxf(mx, v[c2].w);
    }
#pragma unroll
    for (int o = 16; o > 0; o >>= 1) mx = fmaxf(mx, __shfl_xor_sync(0xffffffffu, mx, o));

    float sum = 0.f;
#pragma unroll
    for (int c2 = 0; c2 < 8; c2++) {
        if (c2 >= nch) continue;
        int jb = (c2 << 7) + (lane << 2);
        float e0 = (jb + 0 < valid) ? __expf(v[c2].x - mx) : 0.f;
        float e1 = (jb + 1 < valid) ? __expf(v[c2].y - mx) : 0.f;
        float e2 = (jb + 2 < valid) ? __expf(v[c2].z - mx) : 0.f;
        float e3 = (jb + 3 < valid) ? __expf(v[c2].w - mx) : 0.f;
        v[c2].x = e0; v[c2].y = e1; v[c2].z = e2; v[c2].w = e3;
        sum += e0 + e1 + e2 + e3;
    }
#pragma unroll
    for (int o = 16; o > 0; o >>= 1) sum += __shfl_xor_sync(0xffffffffu, sum, o);
    float rs = 1.0f / sum;
#pragma unroll
    for (int c2 = 0; c2 < 8; c2++) {
        if (c2 >= nch) continue;
        int jb = (c2 << 7) + (lane << 2);
        v[c2].x *= rs; v[c2].y *= rs; v[c2].z *= rs; v[c2].w *= rs;
        *(float4*)(p + jb) = v[c2];
    }
}

// ---------------- LayerNorm over last dim (128) ----------------
__global__ __launch_bounds__(256) void ln_kernel(
    const float* __restrict__ Y, const float* __restrict__ gamma,
    const float* __restrict__ beta, float* __restrict__ out)
{
    const int row  = (blockIdx.x << 3) + (threadIdx.x >> 5);
    const int lane = threadIdx.x & 31;
    const float* y = Y + (long)row * 128;

    float4 v = *(const float4*)(y + (lane << 2));
    float s = v.x + v.y + v.z + v.w;
#pragma unroll
    for (int o = 16; o > 0; o >>= 1) s += __shfl_xor_sync(0xffffffffu, s, o);
    float mu = s * (1.0f / 128.0f);

    float dx = v.x - mu, dy = v.y - mu, dz = v.z - mu, dw = v.w - mu;
    float q = dx * dx + dy * dy + dz * dz + dw * dw;
#pragma unroll
    for (int o = 16; o > 0; o >>= 1) q += __shfl_xor_sync(0xffffffffu, q, o);
    float inv = rsqrtf(q * (1.0f / 128.0f) + 1e-5f);

    float4 g  = *(const float4*)(gamma + (lane << 2));
    float4 b4 = *(const float4*)(beta + (lane << 2));
    float4 o4;
    o4.x = dx * inv * g.x + b4.x;
    o4.y = dy * inv * g.y + b4.y;
    o4.z = dz * inv * g.z + b4.z;
    o4.w = dw * inv * g.w + b4.w;
    *(float4*)(out + (long)row * 128 + (lane << 2)) = o4;
}

// ---------------- launch ----------------
extern "C" void kernel_launch(void* const* d_in, const int* in_sizes, int n_in,
                              void* d_out, int out_size)
{
    const float* x     = (const float*)d_in[0];
    const float* mem   = (const float*)d_in[1];
    const float* R     = (const float*)d_in[2];
    // d_in[3] = att_mask (all ones; unused by reference)
    const float* u1    = (const float*)d_in[4];
    const float* u2    = (const float*)d_in[5];
    const float* Wq    = (const float*)d_in[6];
    const float* Wkv   = (const float*)d_in[7];
    const float* Wr    = (const float*)d_in[8];
    const float* Wmlp  = (const float*)d_in[9];
    const float* gamma = (const float*)d_in[10];
    const float* beta  = (const float*)d_in[11];
    float* out = (float*)d_out;

    float *hb, *qf, *kvf, *rf, *gg, *sb, *att, *yb;
    cudaGetSymbolAddress((void**)&hb,  g_h);
    cudaGetSymbolAddress((void**)&qf,  g_qf);
    cudaGetSymbolAddress((void**)&kvf, g_kvf);
    cudaGetSymbolAddress((void**)&rf,  g_rf);
    cudaGetSymbolAddress((void**)&gg,  g_g);
    cudaGetSymbolAddress((void**)&sb,  g_s);
    cudaGetSymbolAddress((void**)&att, g_att);
    cudaGetSymbolAddress((void**)&yb,  g_y);

    // 1) h = concat(mem, x)
    concat_kernel<<<2048, 256>>>(x, mem, hb);
    // 2) qf = x @ Wq            (8192 x 1024, K=128)
    gemm_tf32<<<dim3(8, 64, 1), 256>>>(x, Wq, qf, 8192, 1024, 128, 0, 0, 0, nullptr, 0);
    // 3) kvf = h @ Wkv          (16384 x 2048, K=128)
    gemm_tf32<<<dim3(16, 128, 1), 256>>>(hb, Wkv, kvf, 16384, 2048, 128, 0, 0, 0, nullptr, 0);
    // 4) rf = R @ Wr            (1024 x 1024, K=128)
    gemm_tf32<<<dim3(8, 8, 1), 256>>>(R, Wr, rf, 1024, 1024, 128, 0, 0, 0, nullptr, 0);
    // 5) G = (q + u2) @ r^T     per z: 512 x 1024 (banded tiles only)
    gemm_nt_g<<<dim3(8, 4, 128), 256>>>(qf, rf, u2, gg);
    // 6) S = ((q+u1)@k^T + gather(G)) / sqrt(d), causal band only
    score_ac<<<dim3(16, 8, 128), 256>>>(qf, kvf, gg, u1, sb);
    // 7) P = softmax(S), banded
    softmax_kernel<<<8192, 256>>>(sb);
    // 8) att = P @ V            per z: 512 x 128, K capped at m0+640
    gemm_tf32<<<dim3(1, 4, 128), 256>>>(sb, kvf + 16777216L, att,
                                        512, 128, 1024, 524288L, 131072L, 65536L, nullptr, 640);
    // 9) y = att @ Wmlp + x     (8192 x 128, K=1024)
    gemm_tf32<<<dim3(1, 64, 1), 256>>>(att, Wmlp, yb, 8192, 128, 1024, 0, 0, 0, x, 0);
    // 10) out = LayerNorm(y) * gamma + beta
    ln_kernel<<<1024, 256>>>(yb, gamma, beta, out);
}

// round 6
// speedup vs baseline: 1.3795x; 1.1042x over previous
#include <cuda_runtime.h>
#include <math.h>
#include <stdint.h>

// Problem constants: B=16, SEG=512, MEM=512, TOTAL=1024, MD=128, H=8, D=128

// ---------------- scratch ----------------
__device__ float g_h   [16 * 1024 * 128];          // concat(mem,x)      8 MB
__device__ float g_qf  [16 * 512 * 1024];          // x@Wq              32 MB
__device__ float g_kvf [16 * 1024 * 2048];         // h@Wkv            128 MB
__device__ float g_rf  [1024 * 1024];              // R@Wr               4 MB
__device__ float g_g   [128ll * 512 * 1024];       // G=(q+u2)@r^T     256 MB
__device__ float g_att [16 * 512 * 1024];          // attention out     32 MB
__device__ float g_y   [16 * 512 * 128];           // pre-LN y           4 MB

// ---------------- tf32 helpers ----------------
__device__ __forceinline__ uint32_t f2tf(float f) {
    uint32_t u; asm("cvt.rna.tf32.f32 %0, %1;" : "=r"(u) : "f"(f)); return u;
}
__device__ __forceinline__ uint4 cvt4(float4 v) {
    return make_uint4(f2tf(v.x), f2tf(v.y), f2tf(v.z), f2tf(v.w));
}
__device__ __forceinline__ float4 add4(float4 a, float4 b) {
    return make_float4(a.x + b.x, a.y + b.y, a.z + b.z, a.w + b.w);
}
__device__ __forceinline__ void mma8(float4& c, const uint32_t a[4], uint32_t b0, uint32_t b1) {
    asm volatile("mma.sync.aligned.m16n8k8.row.col.f32.tf32.tf32.f32 "
        "{%0,%1,%2,%3}, {%4,%5,%6,%7}, {%8,%9}, {%0,%1,%2,%3};"
        : "+f"(c.x), "+f"(c.y), "+f"(c.z), "+f"(c.w)
        : "r"(a[0]), "r"(a[1]), "r"(a[2]), "r"(a[3]), "r"(b0), "r"(b1));
}

// ---------------- concat(mem, x) -> g_h ----------------
__global__ __launch_bounds__(256) void concat_kernel(
    const float* __restrict__ x, const float* __restrict__ mem, float* __restrict__ hout)
{
    long idx = (long)blockIdx.x * blockDim.x + threadIdx.x;
    long e = idx * 4;
    int b   = (int)(e >> 17);
    int rem = (int)(e & 131071);
    float4 v;
    if (rem < 65536)  v = *(const float4*)(mem + (long)b * 65536 + rem);
    else              v = *(const float4*)(x   + (long)b * 65536 + rem - 65536);
    *(float4*)(hout + e) = v;
}

// ---------------- tf32 NN GEMM (block 128x128, BK=32, 256 thr) ----------------
__global__ __launch_bounds__(256) void gemm_tf32(
    const float* __restrict__ Ab, const float* __restrict__ Bb, float* __restrict__ Cb,
    int M, int N, int K, long sA, long sB, long sC, const float* __restrict__ resid)
{
    const float* A = Ab + (long)blockIdx.z * sA;
    const float* B = Bb + (long)blockIdx.z * sB;
    float*       C = Cb + (long)blockIdx.z * sC;

    __shared__ __align__(16) uint32_t As[128 * 36];
    __shared__ __align__(16) uint32_t Bs[32 * 132];

    const int tid = threadIdx.x, lane = tid & 31, wid = tid >> 5;
    const int m0 = blockIdx.y << 7, n0 = blockIdx.x << 7;
    const int wm = (wid & 1) << 6;
    const int wn = (wid >> 1) << 5;
    const int g = lane >> 2, lt = lane & 3;

    const int am = tid >> 3, ak = (tid & 7) << 2;
    const int bk = tid >> 5, bn = (tid & 31) << 2;

    float4 acc[4][4];
#pragma unroll
    for (int t = 0; t < 4; t++)
#pragma unroll
        for (int s = 0; s < 4; s++) acc[t][s] = make_float4(0.f, 0.f, 0.f, 0.f);

    for (int k0 = 0; k0 < K; k0 += 32) {
        uint4 ta[4], tb[4];
#pragma unroll
        for (int it = 0; it < 4; it++) {
            ta[it] = cvt4(*(const float4*)(A + (long)(m0 + am + (it << 5)) * K + k0 + ak));
            tb[it] = cvt4(*(const float4*)(B + (long)(k0 + bk + (it << 3)) * N + n0 + bn));
        }
        __syncthreads();
#pragma unroll
        for (int it = 0; it < 4; it++) {
            *(uint4*)&As[(am + (it << 5)) * 36 + ak] = ta[it];
            *(uint4*)&Bs[(bk + (it << 3)) * 132 + bn] = tb[it];
        }
        __syncthreads();
#pragma unroll
        for (int kk = 0; kk < 4; kk++) {
            const int kb = kk << 3;
            uint32_t af[4][4];
#pragma unroll
            for (int t = 0; t < 4; t++) {
                int row = wm + (t << 4) + g;
                af[t][0] = As[row * 36 + kb + lt];
                af[t][1] = As[(row + 8) * 36 + kb + lt];
                af[t][2] = As[row * 36 + kb + lt + 4];
                af[t][3] = As[(row + 8) * 36 + kb + lt + 4];
            }
#pragma unroll
            for (int s = 0; s < 4; s++) {
                int col = wn + (s << 3) + g;
                uint32_t b0 = Bs[(kb + lt) * 132 + col];
                uint32_t b1 = Bs[(kb + lt + 4) * 132 + col];
#pragma unroll
                for (int t = 0; t < 4; t++) mma8(acc[t][s], af[t], b0, b1);
            }
        }
    }

#pragma unroll
    for (int t = 0; t < 4; t++) {
        int r0 = m0 + wm + (t << 4) + g;
#pragma unroll
        for (int s = 0; s < 4; s++) {
            int c = n0 + wn + (s << 3) + (lt << 1);
            float2 v0 = make_float2(acc[t][s].x, acc[t][s].y);
            float2 v1 = make_float2(acc[t][s].z, acc[t][s].w);
            if (resid) {
                float2 r4 = *(const float2*)(resid + (long)r0 * N + c);
                v0.x += r4.x; v0.y += r4.y;
                float2 r5 = *(const float2*)(resid + (long)(r0 + 8) * N + c);
                v1.x += r5.x; v1.y += r5.y;
            }
            *(float2*)(C + (long)r0 * N + c) = v0;
            *(float2*)(C + (long)(r0 + 8) * N + c) = v1;
        }
    }
}

// ---------------- G = (q + u2) @ r^T, per z (512 x 1024), tf32 NT GEMM ----------------
__global__ __launch_bounds__(256) void gemm_nt_g(
    const float* __restrict__ qf, const float* __restrict__ rf,
    const float* __restrict__ U2, float* __restrict__ Gg)
{
    const int r0 = blockIdx.y << 7, c0 = blockIdx.x << 7;
    if (r0 + c0 + 254 < 511) return;     // never-used region of G
    const int z = blockIdx.z, h = z & 7;
    const float* A  = qf + (long)z * 65536;
    const float* Bm = rf + (long)h * 131072;
    float*       G  = Gg + (long)z * 524288;

    __shared__ __align__(16) uint32_t As[128 * 36];   // [m][k]
    __shared__ __align__(16) uint32_t Bs[128 * 36];   // [n][k]
    __shared__ float u2s[128];

    const int tid = threadIdx.x, lane = tid & 31, wid = tid >> 5;
    const int wm = (wid & 1) << 6;
    const int wn = (wid >> 1) << 5;
    const int g = lane >> 2, lt = lane & 3;
    const int am = tid >> 3, ak = (tid & 7) << 2;

    if (tid < 128) u2s[tid] = U2[(h << 7) + tid];
    __syncthreads();

    float4 acc[4][4];
#pragma unroll
    for (int t = 0; t < 4; t++)
#pragma unroll
        for (int s = 0; s < 4; s++) acc[t][s] = make_float4(0.f, 0.f, 0.f, 0.f);

#pragma unroll
    for (int k0 = 0; k0 < 128; k0 += 32) {
        float4 u4 = *(const float4*)&u2s[k0 + ak];
        uint4 ta[4], tb[4];
#pragma unroll
        for (int it = 0; it < 4; it++) {
            float4 av = *(const float4*)(A  + (long)(r0 + am + (it << 5)) * 128 + k0 + ak);
            ta[it] = cvt4(add4(av, u4));
            tb[it] = cvt4(*(const float4*)(Bm + (long)(c0 + am + (it << 5)) * 128 + k0 + ak));
        }
        __syncthreads();
#pragma unroll
        for (int it = 0; it < 4; it++) {
            *(uint4*)&As[(am + (it << 5)) * 36 + ak] = ta[it];
            *(uint4*)&Bs[(am + (it << 5)) * 36 + ak] = tb[it];
        }
        __syncthreads();
#pragma unroll
        for (int kk = 0; kk < 4; kk++) {
            const int kb = kk << 3;
            uint32_t af[4][4];
#pragma unroll
            for (int t = 0; t < 4; t++) {
                int row = wm + (t << 4) + g;
                af[t][0] = As[row * 36 + kb + lt];
                af[t][1] = As[(row + 8) * 36 + kb + lt];
                af[t][2] = As[row * 36 + kb + lt + 4];
                af[t][3] = As[(row + 8) * 36 + kb + lt + 4];
            }
#pragma unroll
            for (int s = 0; s < 4; s++) {
                int n = (wn + (s << 3) + g) * 36 + kb + lt;
                uint32_t b0 = Bs[n], b1 = Bs[n + 4];
#pragma unroll
                for (int t = 0; t < 4; t++) mma8(acc[t][s], af[t], b0, b1);
            }
        }
    }

#pragma unroll
    for (int t = 0; t < 4; t++) {
        int rr = r0 + wm + (t << 4) + g;
#pragma unroll
        for (int s = 0; s < 4; s++) {
            int c = c0 + wn + (s << 3) + (lt << 1);
            *(float2*)(G + (long)rr * 1024 + c) = make_float2(acc[t][s].x, acc[t][s].y);
            *(float2*)(G + (long)(rr + 8) * 1024 + c) = make_float2(acc[t][s].z, acc[t][s].w);
        }
    }
}

// ---------------- fused flash: S=(q+u1)K^T + gather(G) -> online softmax -> P@V ----------------
// Grid (8 i-tiles, 128 z); block = 128 threads = 4 warps; warp owns 16 full rows.
// Smem: Ps [64][68] @0 (17408 B); Ks [64][132] / Vs [64][136] overlay @17408 (34816 B). Total 52224.
#define FLASH_SMEM 52224

__global__ __launch_bounds__(128) void flash_pv(
    const float* __restrict__ qf, const float* __restrict__ kvf,
    const float* __restrict__ Gg, const float* __restrict__ U1,
    float* __restrict__ att)
{
    extern __shared__ char dsm[];
    uint32_t* Ps = (uint32_t*)dsm;                  // [64][68]
    uint32_t* Ks = (uint32_t*)(dsm + 17408);        // [64][132] (n=K-row, k)
    uint32_t* Vs = (uint32_t*)(dsm + 17408);        // [64][136] (k=V-row, n=d) overlay

    const int it = blockIdx.x, z = blockIdx.y, h = z & 7;
    const int i0 = it << 6;
    const float* Q  = qf  + (long)z * 65536;
    const float* Kg = kvf + (long)z * 131072;
    const float* Vg = kvf + 16777216L + (long)z * 131072;
    const float* Gz = Gg  + (long)z * 524288;
    const float* u1 = U1  + (h << 7);

    const int tid = threadIdx.x, lane = tid & 31, w = tid >> 5;
    const int g = lane >> 2, lt = lane & 3;
    const int wm = w << 4;
    const int iA = i0 + wm + g, iB = iA + 8;        // global rows (0..511)

    // Q as resident A-fragments: Qreg[kc*4 + {0..3}]
    uint32_t Qreg[64];
#pragma unroll
    for (int kc = 0; kc < 16; kc++) {
        int k0 = kc << 3;
        float ua = u1[k0 + lt], ub = u1[k0 + lt + 4];
        Qreg[kc * 4 + 0] = f2tf(Q[(long)iA * 128 + k0 + lt] + ua);
        Qreg[kc * 4 + 1] = f2tf(Q[(long)iB * 128 + k0 + lt] + ua);
        Qreg[kc * 4 + 2] = f2tf(Q[(long)iA * 128 + k0 + lt + 4] + ub);
        Qreg[kc * 4 + 3] = f2tf(Q[(long)iB * 128 + k0 + lt + 4] + ub);
    }

    float4 on[16];
#pragma unroll
    for (int n = 0; n < 16; n++) on[n] = make_float4(0.f, 0.f, 0.f, 0.f);
    float mA = -1e30f, mB = -1e30f, lA = 0.f, lB = 0.f;

    const float inv = 0.08838834764831845f;         // 1/sqrt(128)
    const float* GA = Gz + (long)iA * 1024 + 511 - iA;
    const float* GB = Gz + (long)iB * 1024 + 511 - iB;
    const int capA = iA + 512, capB = iB + 512;     // j valid iff j <= cap
    const int njt = it + 9;

    const int sr = tid >> 1, sc0 = (tid & 1) << 2;  // staging: row, col base (8-col stride per f)

    for (int jt = 0; jt < njt; jt++) {
        const int j0 = jt << 6;

        // ---- stage K tile: Ks[n][k] = tf32(K[j0+n][k]) ----
        __syncthreads();
#pragma unroll
        for (int f = 0; f < 16; f++) {
            int k = sc0 + (f << 3);
            *(uint4*)&Ks[sr * 132 + k] = cvt4(*(const float4*)(Kg + (long)(j0 + sr) * 128 + k));
        }
        __syncthreads();

        // ---- AC mma: acS[s] covers cols j0 + s*8 + {2lt,2lt+1}, rows iA/iB ----
        float4 acS[8];
#pragma unroll
        for (int s = 0; s < 8; s++) acS[s] = make_float4(0.f, 0.f, 0.f, 0.f);
#pragma unroll
        for (int kc = 0; kc < 16; kc++) {
            const uint32_t* a = &Qreg[kc << 2];
            int kb = kc << 3;
#pragma unroll
            for (int s = 0; s < 8; s++) {
                int n = ((s << 3) + g) * 132 + kb + lt;
                mma8(acS[s], a, Ks[n], Ks[n + 4]);
            }
        }

        // ---- add gathered G, scale, mask; row max ----
        float mxA = -1e30f, mxB = -1e30f;
#pragma unroll
        for (int s = 0; s < 8; s++) {
            int j = j0 + (s << 3) + (lt << 1);
            float g0 = (j     <= capA) ? GA[j]     : 0.f;
            float g1 = (j + 1 <= capA) ? GA[j + 1] : 0.f;
            float g2 = (j     <= capB) ? GB[j]     : 0.f;
            float g3 = (j + 1 <= capB) ? GB[j + 1] : 0.f;
            acS[s].x = (j     <= capA) ? (acS[s].x + g0) * inv : -1e30f;
            acS[s].y = (j + 1 <= capA) ? (acS[s].y + g1) * inv : -1e30f;
            acS[s].z = (j     <= capB) ? (acS[s].z + g2) * inv : -1e30f;
            acS[s].w = (j + 1 <= capB) ? (acS[s].w + g3) * inv : -1e30f;
            mxA = fmaxf(mxA, fmaxf(acS[s].x, acS[s].y));
            mxB = fmaxf(mxB, fmaxf(acS[s].z, acS[s].w));
        }
        mxA = fmaxf(mxA, __shfl_xor_sync(0xffffffffu, mxA, 1));
        mxA = fmaxf(mxA, __shfl_xor_sync(0xffffffffu, mxA, 2));
        mxB = fmaxf(mxB, __shfl_xor_sync(0xffffffffu, mxB, 1));
        mxB = fmaxf(mxB, __shfl_xor_sync(0xffffffffu, mxB, 2));

        float mnA = fmaxf(mA, mxA), mnB = fmaxf(mB, mxB);
        float fA = __expf(mA - mnA), fB = __expf(mB - mnB);
        mA = mnA; mB = mnB;

        // ---- P = exp(S - m), partial sums, store P to per-warp smem ----
        float sA = 0.f, sB = 0.f;
#pragma unroll
        for (int s = 0; s < 8; s++) {
            int c = (s << 3) + (lt << 1);
            float p0 = __expf(acS[s].x - mnA);
            float p1 = __expf(acS[s].y - mnA);
            float p2 = __expf(acS[s].z - mnB);
            float p3 = __expf(acS[s].w - mnB);
            sA += p0 + p1; sB += p2 + p3;
            Ps[(wm + g) * 68 + c]     = f2tf(p0);
            Ps[(wm + g) * 68 + c + 1] = f2tf(p1);
            Ps[(wm + g + 8) * 68 + c]     = f2tf(p2);
            Ps[(wm + g + 8) * 68 + c + 1] = f2tf(p3);
        }
        sA += __shfl_xor_sync(0xffffffffu, sA, 1);
        sA += __shfl_xor_sync(0xffffffffu, sA, 2);
        sB += __shfl_xor_sync(0xffffffffu, sB, 1);
        sB += __shfl_xor_sync(0xffffffffu, sB, 2);
        lA = lA * fA + sA;
        lB = lB * fB + sB;

        // rescale O
#pragma unroll
        for (int n = 0; n < 16; n++) {
            on[n].x *= fA; on[n].y *= fA; on[n].z *= fB; on[n].w *= fB;
        }
        __syncwarp();

        // ---- stage V tile (overlay on Ks): Vs[k=jrow][n=d] ----
        __syncthreads();
#pragma unroll
        for (int f = 0; f < 16; f++) {
            int c = sc0 + (f << 3);
            *(uint4*)&Vs[sr * 136 + c] = cvt4(*(const float4*)(Vg + (long)(j0 + sr) * 128 + c));
        }
        __syncthreads();

        // ---- PV mma: O += P @ V ----
#pragma unroll
        for (int kc = 0; kc < 8; kc++) {
            int kb = kc << 3;
            uint32_t a[4] = { Ps[(wm + g) * 68 + kb + lt],
                              Ps[(wm + g + 8) * 68 + kb + lt],
                              Ps[(wm + g) * 68 + kb + lt + 4],
                              Ps[(wm + g + 8) * 68 + kb + lt + 4] };
#pragma unroll
            for (int n = 0; n < 16; n++) {
                int c = (n << 3) + g;
                mma8(on[n], a, Vs[(kb + lt) * 136 + c], Vs[(kb + lt + 4) * 136 + c]);
            }
        }
    }

    // ---- epilogue: O / l -> att (flat z-major layout) ----
    float ivA = 1.f / lA, ivB = 1.f / lB;
    float* ap = att + (long)z * 65536;
#pragma unroll
    for (int n = 0; n < 16; n++) {
        int c = (n << 3) + (lt << 1);
        *(float2*)(ap + (long)iA * 128 + c) = make_float2(on[n].x * ivA, on[n].y * ivA);
        *(float2*)(ap + (long)iB * 128 + c) = make_float2(on[n].z * ivB, on[n].w * ivB);
    }
}

// ---------------- LayerNorm over last dim (128) ----------------
__global__ __launch_bounds__(256) void ln_kernel(
    const float* __restrict__ Y, const float* __restrict__ gamma,
    const float* __restrict__ beta, float* __restrict__ out)
{
    const int row  = (blockIdx.x << 3) + (threadIdx.x >> 5);
    const int lane = threadIdx.x & 31;
    const float* y = Y + (long)row * 128;

    float4 v = *(const float4*)(y + (lane << 2));
    float s = v.x + v.y + v.z + v.w;
#pragma unroll
    for (int o = 16; o > 0; o >>= 1) s += __shfl_xor_sync(0xffffffffu, s, o);
    float mu = s * (1.0f / 128.0f);

    float dx = v.x - mu, dy = v.y - mu, dz = v.z - mu, dw = v.w - mu;
    float q = dx * dx + dy * dy + dz * dz + dw * dw;
#pragma unroll
    for (int o = 16; o > 0; o >>= 1) q += __shfl_xor_sync(0xffffffffu, q, o);
    float inv = rsqrtf(q * (1.0f / 128.0f) + 1e-5f);

    float4 g  = *(const float4*)(gamma + (lane << 2));
    float4 b4 = *(const float4*)(beta + (lane << 2));
    float4 o4;
    o4.x = dx * inv * g.x + b4.x;
    o4.y = dy * inv * g.y + b4.y;
    o4.z = dz * inv * g.z + b4.z;
    o4.w = dw * inv * g.w + b4.w;
    *(float4*)(out + (long)row * 128 + (lane << 2)) = o4;
}

// ---------------- launch ----------------
extern "C" void kernel_launch(void* const* d_in, const int* in_sizes, int n_in,
                              void* d_out, int out_size)
{
    const float* x     = (const float*)d_in[0];
    const float* mem   = (const float*)d_in[1];
    const float* R     = (const float*)d_in[2];
    // d_in[3] = att_mask (all ones; unused by reference)
    const float* u1    = (const float*)d_in[4];
    const float* u2    = (const float*)d_in[5];
    const float* Wq    = (const float*)d_in[6];
    const float* Wkv   = (const float*)d_in[7];
    const float* Wr    = (const float*)d_in[8];
    const float* Wmlp  = (const float*)d_in[9];
    const float* gamma = (const float*)d_in[10];
    const float* beta  = (const float*)d_in[11];
    float* out = (float*)d_out;

    float *hb, *qf, *kvf, *rf, *gg, *att, *yb;
    cudaGetSymbolAddress((void**)&hb,  g_h);
    cudaGetSymbolAddress((void**)&qf,  g_qf);
    cudaGetSymbolAddress((void**)&kvf, g_kvf);
    cudaGetSymbolAddress((void**)&rf,  g_rf);
    cudaGetSymbolAddress((void**)&gg,  g_g);
    cudaGetSymbolAddress((void**)&att, g_att);
    cudaGetSymbolAddress((void**)&yb,  g_y);

    cudaFuncSetAttribute(flash_pv, cudaFuncAttributeMaxDynamicSharedMemorySize, FLASH_SMEM);

    // 1) h = concat(mem, x)
    concat_kernel<<<2048, 256>>>(x, mem, hb);
    // 2) qf = x @ Wq            (8192 x 1024, K=128)
    gemm_tf32<<<dim3(8, 64, 1), 256>>>(x, Wq, qf, 8192, 1024, 128, 0, 0, 0, nullptr);
    // 3) kvf = h @ Wkv          (16384 x 2048, K=128)
    gemm_tf32<<<dim3(16, 128, 1), 256>>>(hb, Wkv, kvf, 16384, 2048, 128, 0, 0, 0, nullptr);
    // 4) rf = R @ Wr            (1024 x 1024, K=128)
    gemm_tf32<<<dim3(8, 8, 1), 256>>>(R, Wr, rf, 1024, 1024, 128, 0, 0, 0, nullptr);
    // 5) G = (q + u2) @ r^T     per z: 512 x 1024 (banded tiles only)
    gemm_nt_g<<<dim3(8, 4, 128), 256>>>(qf, rf, u2, gg);
    // 6) fused: S = ((q+u1)K^T + gather(G))/sqrt(d) -> online softmax -> att = P@V
    flash_pv<<<dim3(8, 128), 128, FLASH_SMEM>>>(qf, kvf, gg, u1, att);
    // 7) y = att @ Wmlp + x     (8192 x 128, K=1024)
    gemm_tf32<<<dim3(1, 64, 1), 256>>>(att, Wmlp, yb, 8192, 128, 1024, 0, 0, 0, x);
    // 8) out = LayerNorm(y) * gamma + beta
    ln_kernel<<<1024, 256>>>(yb, gamma, beta, out);
}